// round 8
// baseline (speedup 1.0000x reference)
#include <cuda_runtime.h>

// EdgeNet v8: ONE-PASS kernel. 512 blocks x 256 threads; block b owns edges
// [64b, 64b+64). Threads = 16 node-phases x 16 float4-columns; each thread
// streams its phase's 512 nodes (full coalescing preserved). Cross-phase
// reduction + MLP happen in shared memory -> zero global partial traffic,
// no second launch.

#define N_NODES 8192
#define N_EDGES 32768
#define E4      (N_EDGES / 4)        // 8192 float4 columns
#define CPB     16                   // float4 columns per block
#define EPB     64                   // edges per block
#define PHASES  16                   // node phases (threads/column)
#define NPP     (N_NODES / PHASES)   // 512 nodes per phase
#define NTHREADS 256
#define NBLOCKS (E4 / CPB)           // 512
#define NHID    100

__device__ __forceinline__ void fma4(float4& a, float s, const float4& x) {
    a.x = fmaf(s, x.x, a.x);
    a.y = fmaf(s, x.y, a.y);
    a.z = fmaf(s, x.z, a.z);
    a.w = fmaf(s, x.w, a.w);
}
__device__ __forceinline__ float fast_tanh(float x) {
    float e = __expf(2.0f * x);
    return 1.0f - __fdividef(2.0f, e + 1.0f);
}

__global__ __launch_bounds__(NTHREADS, 4)
void edgenet_onepass_kernel(const float* __restrict__ X,
                            const float* __restrict__ Ri,
                            const float* __restrict__ Ro,
                            const float* __restrict__ W1,
                            const float* __restrict__ b1,
                            const float* __restrict__ W2,
                            const float* __restrict__ b2,
                            float* __restrict__ out)
{
    // [phase][col][q*8+f] ; row 33 floats -> conflict-free stride
    __shared__ float sRed[PHASES][CPB][33];          // 33.8 KB
    __shared__ float sB[EPB][9];                     // reduced edge features
    __shared__ float sAcc[4][EPB];
    __shared__ __align__(16) float sW1t[NHID][8];
    __shared__ float sb1[NHID];
    __shared__ float sW2[NHID];

    const int tid = threadIdx.x;
    const int c   = tid & (CPB - 1);                 // float4 column 0..15
    const int p   = tid >> 4;                        // node phase 0..15

    // Stage MLP weights up front (overlaps first stream loads).
    for (int i = tid; i < 8 * NHID; i += NTHREADS) {
        int k = i / NHID, j = i % NHID;              // W1 is [8,100] row-major
        sW1t[j][k] = W1[i];
    }
    for (int i = tid; i < NHID; i += NTHREADS) {
        sb1[i] = b1[i];
        sW2[i] = W2[i];
    }

    const float4* __restrict__ X4 = (const float4*)X;
    const int col = blockIdx.x * CPB + c;
    const float4* __restrict__ ro_p = (const float4*)Ro + (size_t)p * E4 + col;
    const float4* __restrict__ ri_p = (const float4*)Ri + (size_t)p * E4 + col;
    const size_t step = (size_t)PHASES * E4;

    float4 ao0 = {0,0,0,0}, ao1 = {0,0,0,0}, ao2 = {0,0,0,0}, ao3 = {0,0,0,0};
    float4 ai0 = {0,0,0,0}, ai1 = {0,0,0,0}, ai2 = {0,0,0,0}, ai3 = {0,0,0,0};

    #pragma unroll 4
    for (int it = 0; it < NPP; ++it) {
        const float4 ro = __ldcs(ro_p); ro_p += step;     // stream-once
        const float4 ri = __ldcs(ri_p); ri_p += step;
        const float4 x  = __ldg(&X4[(it << 4) + p]);      // L2-resident, half-warp bcast
        fma4(ao0, ro.x, x);  fma4(ao1, ro.y, x);
        fma4(ao2, ro.z, x);  fma4(ao3, ro.w, x);
        fma4(ai0, ri.x, x);  fma4(ai1, ri.y, x);
        fma4(ai2, ri.z, x);  fma4(ai3, ri.w, x);
    }

    // Park per-phase partials in smem. Layout [p][c][q*8 + f], f<4 = bo, f>=4 = bi.
    {
        float* r = &sRed[p][c][0];
        r[ 0] = ao0.x; r[ 1] = ao0.y; r[ 2] = ao0.z; r[ 3] = ao0.w;
        r[ 4] = ai0.x; r[ 5] = ai0.y; r[ 6] = ai0.z; r[ 7] = ai0.w;
        r[ 8] = ao1.x; r[ 9] = ao1.y; r[10] = ao1.z; r[11] = ao1.w;
        r[12] = ai1.x; r[13] = ai1.y; r[14] = ai1.z; r[15] = ai1.w;
        r[16] = ao2.x; r[17] = ao2.y; r[18] = ao2.z; r[19] = ao2.w;
        r[20] = ai2.x; r[21] = ai2.y; r[22] = ai2.z; r[23] = ai2.w;
        r[24] = ao3.x; r[25] = ao3.y; r[26] = ao3.z; r[27] = ao3.w;
        r[28] = ai3.x; r[29] = ai3.y; r[30] = ai3.z; r[31] = ai3.w;
    }
    __syncthreads();

    // Cross-phase reduction: 512 (edge,feat) sums, 2 per thread, 16 adds each.
    // Exact: one-hot columns mean at most one phase contributes a nonzero.
    #pragma unroll
    for (int h = 0; h < 2; ++h) {
        const int i  = tid + h * NTHREADS;           // 0..511
        const int cc = i >> 5;                       // column
        const int o  = i & 31;                       // q*8 + f
        float v = 0.0f;
        #pragma unroll
        for (int pp = 0; pp < PHASES; ++pp)
            v += sRed[pp][cc][o];
        const int edge = cc * 4 + (o >> 3);          // local edge 0..63
        sB[edge][o & 7] = v;
    }
    __syncthreads();

    // MLP: 4 threads per edge, 25 hidden units each.
    const int el  = tid & (EPB - 1);
    const int sub = tid >> 6;
    float B0 = sB[el][0], B1 = sB[el][1], B2 = sB[el][2], B3 = sB[el][3];
    float B4 = sB[el][4], B5 = sB[el][5], B6 = sB[el][6], B7 = sB[el][7];

    float acc = 0.0f;
    #pragma unroll 5
    for (int k = 0; k < NHID / 4; ++k) {
        const int j = sub * (NHID / 4) + k;
        const float4 w0 = *(const float4*)&sW1t[j][0];
        const float4 w1 = *(const float4*)&sW1t[j][4];
        float s = sb1[j];
        s = fmaf(B0, w0.x, s);
        s = fmaf(B1, w0.y, s);
        s = fmaf(B2, w0.z, s);
        s = fmaf(B3, w0.w, s);
        s = fmaf(B4, w1.x, s);
        s = fmaf(B5, w1.y, s);
        s = fmaf(B6, w1.z, s);
        s = fmaf(B7, w1.w, s);
        acc = fmaf(fast_tanh(s), sW2[j], acc);
    }
    sAcc[sub][el] = acc;
    __syncthreads();

    if (tid < EPB) {
        float a = b2[0] + (sAcc[0][tid] + sAcc[1][tid])
                        + (sAcc[2][tid] + sAcc[3][tid]);
        out[blockIdx.x * EPB + tid] = __fdividef(1.0f, 1.0f + __expf(-a));
    }
}

extern "C" void kernel_launch(void* const* d_in, const int* in_sizes, int n_in,
                              void* d_out, int out_size)
{
    // metadata order: X, Ri, Ro, W1, b1, W2, b2
    const float* X  = (const float*)d_in[0];
    const float* Ri = (const float*)d_in[1];
    const float* Ro = (const float*)d_in[2];
    const float* W1 = (const float*)d_in[3];
    const float* b1 = (const float*)d_in[4];
    const float* W2 = (const float*)d_in[5];
    const float* b2 = (const float*)d_in[6];
    float* out = (float*)d_out;

    edgenet_onepass_kernel<<<NBLOCKS, NTHREADS>>>(X, Ri, Ro, W1, b1, W2, b2, out);
}

// round 9
// speedup vs baseline: 1.1393x; 1.1393x over previous
#include <cuda_runtime.h>

// EdgeNet v9: phase-1 identical to R5 (HBM-ceiling 6.99 TB/s). phase-2
// barrier-free: 4 lanes/edge, shfl_xor butterfly reduction, no smem
// round-trips on the critical path.

#define N_NODES 8192
#define N_EDGES 32768
#define S_SEG   16
#define NODES_PER_SEG (N_NODES / S_SEG)      // 512
#define E4      (N_EDGES / 4)                // 8192 float4 columns
#define A_THREADS 256
#define EGRPS   (E4 / A_THREADS)             // 32 edge-group blocks
#define NHID    100
#define M_THREADS 256

// Per (segment, edge): bo(float4), bi(float4).  16 MB.
__device__ float4 g_partial[(size_t)S_SEG * N_EDGES * 2];

__device__ __forceinline__ void fma4(float4& a, float s, const float4& x) {
    a.x = fmaf(s, x.x, a.x);
    a.y = fmaf(s, x.y, a.y);
    a.z = fmaf(s, x.z, a.z);
    a.w = fmaf(s, x.w, a.w);
}
__device__ __forceinline__ void add4(float4& a, const float4& b) {
    a.x += b.x; a.y += b.y; a.z += b.z; a.w += b.w;
}
__device__ __forceinline__ float fast_tanh(float x) {
    float e = __expf(2.0f * x);
    return 1.0f - __fdividef(2.0f, e + 1.0f);
}

__global__ __launch_bounds__(A_THREADS, 4)
void edgenet_accum_kernel(const float* __restrict__ X,
                          const float* __restrict__ Ri,
                          const float* __restrict__ Ro)
{
    __shared__ float4 sX[NODES_PER_SEG];   // 8 KB

    const int tid = threadIdx.x;
    const int seg = blockIdx.y;
    const int n0  = seg * NODES_PER_SEG;

    const float4* __restrict__ X4 = (const float4*)X;
    for (int i = tid; i < NODES_PER_SEG; i += A_THREADS)
        sX[i] = X4[n0 + i];
    __syncthreads();

    const int e4 = blockIdx.x * A_THREADS + tid;
    const float4* __restrict__ ro_p = (const float4*)Ro + (size_t)n0 * E4 + e4;
    const float4* __restrict__ ri_p = (const float4*)Ri + (size_t)n0 * E4 + e4;

    float4 ao0 = {0,0,0,0}, ao1 = {0,0,0,0}, ao2 = {0,0,0,0}, ao3 = {0,0,0,0};
    float4 ai0 = {0,0,0,0}, ai1 = {0,0,0,0}, ai2 = {0,0,0,0}, ai3 = {0,0,0,0};

    #pragma unroll 4
    for (int n = 0; n < NODES_PER_SEG; ++n) {
        const float4 ro = __ldcs(&ro_p[(size_t)n * E4]);   // stream-once
        const float4 ri = __ldcs(&ri_p[(size_t)n * E4]);
        const float4 x  = sX[n];
        fma4(ao0, ro.x, x);  fma4(ao1, ro.y, x);
        fma4(ao2, ro.z, x);  fma4(ao3, ro.w, x);
        fma4(ai0, ri.x, x);  fma4(ai1, ri.y, x);
        fma4(ai2, ri.z, x);  fma4(ai3, ri.w, x);
    }

    float4* __restrict__ dst = &g_partial[((size_t)seg * N_EDGES + (size_t)e4 * 4) * 2];
    dst[0] = ao0;  dst[1] = ai0;
    dst[2] = ao1;  dst[3] = ai1;
    dst[4] = ao2;  dst[5] = ai2;
    dst[6] = ao3;  dst[7] = ai3;
}

__device__ __forceinline__ void bfly4(float4& a, float4& b, int m) {
    a.x += __shfl_xor_sync(0xFFFFFFFF, a.x, m);
    a.y += __shfl_xor_sync(0xFFFFFFFF, a.y, m);
    a.z += __shfl_xor_sync(0xFFFFFFFF, a.z, m);
    a.w += __shfl_xor_sync(0xFFFFFFFF, a.w, m);
    b.x += __shfl_xor_sync(0xFFFFFFFF, b.x, m);
    b.y += __shfl_xor_sync(0xFFFFFFFF, b.y, m);
    b.z += __shfl_xor_sync(0xFFFFFFFF, b.z, m);
    b.w += __shfl_xor_sync(0xFFFFFFFF, b.w, m);
}

__global__ __launch_bounds__(M_THREADS)
void edgenet_mlp_kernel(const float* __restrict__ W1,
                        const float* __restrict__ b1,
                        const float* __restrict__ W2,
                        const float* __restrict__ b2,
                        float* __restrict__ out)
{
    __shared__ __align__(16) float sW1t[NHID][8];   // W1 transposed [j][k]
    __shared__ float sb1[NHID];
    __shared__ float sW2[NHID];

    const int tid  = threadIdx.x;
    const int lane = tid & 31;
    const int w    = tid >> 5;
    const int sub  = lane & 3;                       // segment quarter 0..3
    // Warp handles 8 edges; lane (4q+sub) owns edge e_base+q, quarter sub.
    const int e    = (blockIdx.x * (M_THREADS >> 5) + w) * 8 + (lane >> 2);

    // ---- Issue this lane's 8 partial loads FIRST (4 segs x [bo,bi]) ----
    const int s0 = sub * 4;
    const float4* p0 = &g_partial[((size_t)(s0 + 0) * N_EDGES + e) * 2];
    const float4* p1 = &g_partial[((size_t)(s0 + 1) * N_EDGES + e) * 2];
    const float4* p2 = &g_partial[((size_t)(s0 + 2) * N_EDGES + e) * 2];
    const float4* p3 = &g_partial[((size_t)(s0 + 3) * N_EDGES + e) * 2];
    float4 o0 = p0[0], i0 = p0[1];
    float4 o1 = p1[0], i1 = p1[1];
    float4 o2 = p2[0], i2 = p2[1];
    float4 o3 = p3[0], i3 = p3[1];

    // ---- Weight staging overlaps the loads above ----
    for (int i = tid; i < 8 * NHID; i += M_THREADS) {
        int k = i / NHID, j = i % NHID;              // W1 is [8,100] row-major
        sW1t[j][k] = W1[i];
    }
    for (int i = tid; i < NHID; i += M_THREADS) {
        sb1[i] = b1[i];
        sW2[i] = W2[i];
    }
    __syncthreads();                                 // weights visible

    add4(o0, o1);  add4(o2, o3);  add4(o0, o2);      // ao for this quarter
    add4(i0, i1);  add4(i2, i3);  add4(i0, i2);      // ai

    // Butterfly across the 4 sub-lanes of each edge (lane^1, lane^2).
    bfly4(o0, i0, 1);
    bfly4(o0, i0, 2);
    // Now every lane holds the full edge feature [bo;bi].

    // MLP: each sub-lane computes 25 hidden units.
    float acc = 0.0f;
    const int jbase = sub * (NHID / 4);
    #pragma unroll 5
    for (int k = 0; k < NHID / 4; ++k) {
        const int j = jbase + k;
        const float4 w0 = *(const float4*)&sW1t[j][0];
        const float4 w1 = *(const float4*)&sW1t[j][4];
        float s = sb1[j];
        s = fmaf(o0.x, w0.x, s);
        s = fmaf(o0.y, w0.y, s);
        s = fmaf(o0.z, w0.z, s);
        s = fmaf(o0.w, w0.w, s);
        s = fmaf(i0.x, w1.x, s);
        s = fmaf(i0.y, w1.y, s);
        s = fmaf(i0.z, w1.z, s);
        s = fmaf(i0.w, w1.w, s);
        acc = fmaf(fast_tanh(s), sW2[j], acc);
    }
    acc += __shfl_xor_sync(0xFFFFFFFF, acc, 1);
    acc += __shfl_xor_sync(0xFFFFFFFF, acc, 2);

    if (sub == 0) {
        float a = acc + __ldg(b2);
        out[e] = __fdividef(1.0f, 1.0f + __expf(-a));
    }
}

extern "C" void kernel_launch(void* const* d_in, const int* in_sizes, int n_in,
                              void* d_out, int out_size)
{
    // metadata order: X, Ri, Ro, W1, b1, W2, b2
    const float* X  = (const float*)d_in[0];
    const float* Ri = (const float*)d_in[1];
    const float* Ro = (const float*)d_in[2];
    const float* W1 = (const float*)d_in[3];
    const float* b1 = (const float*)d_in[4];
    const float* W2 = (const float*)d_in[5];
    const float* b2 = (const float*)d_in[6];
    float* out = (float*)d_out;

    dim3 grid1(EGRPS, S_SEG);              // 32 x 16 = 512 blocks of 256 thr
    edgenet_accum_kernel<<<grid1, A_THREADS>>>(X, Ri, Ro);

    // 4096 warps, 8 edges each -> 512 blocks of 256 thr
    dim3 grid2(N_EDGES / ((M_THREADS >> 5) * 8));
    edgenet_mlp_kernel<<<grid2, M_THREADS>>>(W1, b1, W2, b2, out);
}

// round 10
// speedup vs baseline: 1.1940x; 1.0480x over previous
#include <cuda_runtime.h>

// EdgeNet v10: one-hot-aware reduction. Phase-1 streams Ro/Ri at the HBM
// ceiling, then flushes ONLY nonzero per-segment partials (expected ~6%)
// via predicated atomicAdd into a 1 MB accumulator (exact: each (edge,side)
// has exactly one nonzero segment, landing on a zeroed slot). Phase-2 reads
// the L2-hot accumulator, runs the MLP, and re-zeroes it for graph replay.

#define N_NODES 8192
#define N_EDGES 32768
#define S_SEG   16
#define NODES_PER_SEG (N_NODES / S_SEG)      // 512
#define E4      (N_EDGES / 4)                // 8192 float4 columns
#define A_THREADS 256
#define EGRPS   (E4 / A_THREADS)             // 32 edge-group blocks
#define NHID    100
#define M_THREADS 256

// Direct accumulator: [edge][8] floats (bo.xyzw, bi.xyzw).  1 MB.
// BSS zero-init covers the first run; phase-2 re-zeroes after consuming.
__device__ float g_accum[(size_t)N_EDGES * 8];

__device__ __forceinline__ void fma4(float4& a, float s, const float4& x) {
    a.x = fmaf(s, x.x, a.x);
    a.y = fmaf(s, x.y, a.y);
    a.z = fmaf(s, x.z, a.z);
    a.w = fmaf(s, x.w, a.w);
}
__device__ __forceinline__ float fast_tanh(float x) {
    float e = __expf(2.0f * x);
    return 1.0f - __fdividef(2.0f, e + 1.0f);
}

__device__ __forceinline__ void flush_nz(const float4& v, int e, int half) {
    // Skip all-zero partials (exact: adding zero is a no-op).
    if (v.x != 0.0f || v.y != 0.0f || v.z != 0.0f || v.w != 0.0f) {
        float* a = &g_accum[(size_t)e * 8 + half * 4];
        atomicAdd(a + 0, v.x);
        atomicAdd(a + 1, v.y);
        atomicAdd(a + 2, v.z);
        atomicAdd(a + 3, v.w);
    }
}

__global__ __launch_bounds__(A_THREADS, 4)
void edgenet_accum_kernel(const float* __restrict__ X,
                          const float* __restrict__ Ri,
                          const float* __restrict__ Ro)
{
    __shared__ float4 sX[NODES_PER_SEG];   // 8 KB

    const int tid = threadIdx.x;
    const int seg = blockIdx.y;
    const int n0  = seg * NODES_PER_SEG;

    const float4* __restrict__ X4 = (const float4*)X;
    for (int i = tid; i < NODES_PER_SEG; i += A_THREADS)
        sX[i] = X4[n0 + i];
    __syncthreads();

    const int e4 = blockIdx.x * A_THREADS + tid;
    const float4* __restrict__ ro_p = (const float4*)Ro + (size_t)n0 * E4 + e4;
    const float4* __restrict__ ri_p = (const float4*)Ri + (size_t)n0 * E4 + e4;

    float4 ao0 = {0,0,0,0}, ao1 = {0,0,0,0}, ao2 = {0,0,0,0}, ao3 = {0,0,0,0};
    float4 ai0 = {0,0,0,0}, ai1 = {0,0,0,0}, ai2 = {0,0,0,0}, ai3 = {0,0,0,0};

    #pragma unroll 4
    for (int n = 0; n < NODES_PER_SEG; ++n) {
        const float4 ro = __ldcs(&ro_p[(size_t)n * E4]);   // stream-once
        const float4 ri = __ldcs(&ri_p[(size_t)n * E4]);
        const float4 x  = sX[n];
        fma4(ao0, ro.x, x);  fma4(ao1, ro.y, x);
        fma4(ao2, ro.z, x);  fma4(ao3, ro.w, x);
        fma4(ai0, ri.x, x);  fma4(ai1, ri.y, x);
        fma4(ai2, ri.z, x);  fma4(ai3, ri.w, x);
    }

    // Flush only nonzero partials (~0.5 of 8 groups per thread on average).
    const int eb = e4 * 4;
    flush_nz(ao0, eb + 0, 0);  flush_nz(ai0, eb + 0, 1);
    flush_nz(ao1, eb + 1, 0);  flush_nz(ai1, eb + 1, 1);
    flush_nz(ao2, eb + 2, 0);  flush_nz(ai2, eb + 2, 1);
    flush_nz(ao3, eb + 3, 0);  flush_nz(ai3, eb + 3, 1);
}

__global__ __launch_bounds__(M_THREADS)
void edgenet_mlp_kernel(const float* __restrict__ W1,
                        const float* __restrict__ b1,
                        const float* __restrict__ W2,
                        const float* __restrict__ b2,
                        float* __restrict__ out)
{
    __shared__ __align__(16) float sW1t[NHID][8];   // W1 transposed [j][k]
    __shared__ float sb1[NHID];
    __shared__ float sW2[NHID];

    const int tid  = threadIdx.x;
    const int lane = tid & 31;
    const int w    = tid >> 5;
    const int sub  = lane & 3;                       // hidden-unit quarter
    // Warp handles 8 edges: lanes (4q+sub) share edge e_base+q.
    const int e    = (blockIdx.x * (M_THREADS >> 5) + w) * 8 + (lane >> 2);

    // All 4 sub-lanes load the edge's 8 accumulated features (L2-hot, bcast).
    const float4* acc4 = (const float4*)&g_accum[(size_t)e * 8];
    float4 bo = acc4[0];
    float4 bi = acc4[1];

    // Weight staging overlaps the loads above.
    for (int i = tid; i < 8 * NHID; i += M_THREADS) {
        int k = i / NHID, j = i % NHID;              // W1 is [8,100] row-major
        sW1t[j][k] = W1[i];
    }
    for (int i = tid; i < NHID; i += M_THREADS) {
        sb1[i] = b1[i];
        sW2[i] = W2[i];
    }
    __syncthreads();

    // Each sub-lane computes 25 hidden units.
    float acc = 0.0f;
    const int jbase = sub * (NHID / 4);
    #pragma unroll 5
    for (int k = 0; k < NHID / 4; ++k) {
        const int j = jbase + k;
        const float4 w0 = *(const float4*)&sW1t[j][0];
        const float4 w1 = *(const float4*)&sW1t[j][4];
        float s = sb1[j];
        s = fmaf(bo.x, w0.x, s);
        s = fmaf(bo.y, w0.y, s);
        s = fmaf(bo.z, w0.z, s);
        s = fmaf(bo.w, w0.w, s);
        s = fmaf(bi.x, w1.x, s);
        s = fmaf(bi.y, w1.y, s);
        s = fmaf(bi.z, w1.z, s);
        s = fmaf(bi.w, w1.w, s);
        acc = fmaf(fast_tanh(s), sW2[j], acc);
    }
    acc += __shfl_xor_sync(0xFFFFFFFF, acc, 1);
    acc += __shfl_xor_sync(0xFFFFFFFF, acc, 2);

    if (sub == 0) {
        float a = acc + __ldg(b2);
        out[e] = __fdividef(1.0f, 1.0f + __expf(-a));
        // Re-zero this edge's accumulator for the next graph replay.
        // Safe: all 4 sub-lanes already consumed their loads (shuffles above
        // synchronized them).
        float4* z = (float4*)&g_accum[(size_t)e * 8];
        z[0] = make_float4(0.f, 0.f, 0.f, 0.f);
        z[1] = make_float4(0.f, 0.f, 0.f, 0.f);
    }
}

extern "C" void kernel_launch(void* const* d_in, const int* in_sizes, int n_in,
                              void* d_out, int out_size)
{
    // metadata order: X, Ri, Ro, W1, b1, W2, b2
    const float* X  = (const float*)d_in[0];
    const float* Ri = (const float*)d_in[1];
    const float* Ro = (const float*)d_in[2];
    const float* W1 = (const float*)d_in[3];
    const float* b1 = (const float*)d_in[4];
    const float* W2 = (const float*)d_in[5];
    const float* b2 = (const float*)d_in[6];
    float* out = (float*)d_out;

    dim3 grid1(EGRPS, S_SEG);              // 32 x 16 = 512 blocks of 256 thr
    edgenet_accum_kernel<<<grid1, A_THREADS>>>(X, Ri, Ro);

    // 4096 warps, 8 edges each -> 512 blocks of 256 thr
    dim3 grid2(N_EDGES / ((M_THREADS >> 5) * 8));
    edgenet_mlp_kernel<<<grid2, M_THREADS>>>(W1, b1, W2, b2, out);
}